// round 1
// baseline (speedup 1.0000x reference)
#include <cuda_runtime.h>
#include <math.h>

#define Bn   256
#define IC   1152
#define En   8
#define NC   10
#define DV   16
#define JD   160     // NC*DV

// hat kernel tiling
#define HK_ICHUNK 32
#define HK_NCHUNK (IC / HK_ICHUNK)   // 36
#define HK_BTILE  32
#define HK_NBT    (Bn / HK_BTILE)    // 8

// routing pass kernel tiling
#define PK_ICHUNK 128
#define PK_NCHUNK (IC / PK_ICHUNK)   // 9

// Scratch (static device arrays; no cudaMalloc allowed)
__device__ float g_hat[(size_t)Bn * IC * JD];            // 188.7 MB
__device__ float g_part[(size_t)Bn * HK_NCHUNK * JD];    // 5.9 MB
__device__ float g_u[(size_t)Bn * JD];                   // running sum of v's

// ---------------------------------------------------------------------------
// Kernel 1: compute hat[b,i,j,d] = sum_e x[b,i,e] * W[i,j,e,d], write to g_hat,
// and fold in pass-0 partial sums: s0_partial = sum_{i in chunk} c0[i,j]*hat,
// where c0[i,:] = softmax(bias[i,:]) (batch independent).
// Grid: (36 i-chunks, 8 b-tiles), 256 threads. Warp w owns b_local w*4..w*4+3.
// Lane l owns jd = l + 32k, k<5; j = jd>>4 = 2k + (l>>4).
// ---------------------------------------------------------------------------
__global__ __launch_bounds__(256) void hat_s0_kernel(
    const float* __restrict__ x,     // [B, IC, E]
    const float* __restrict__ W,     // [IC, NC, E, DV]
    const float* __restrict__ bias)  // [1, IC, NC]
{
    const int chunk = blockIdx.x;          // 0..35
    const int bt    = blockIdx.y;          // 0..7
    const int tid   = threadIdx.x;
    const int w     = tid >> 5;
    const int lane  = tid & 31;
    const int i0    = chunk * HK_ICHUNK;
    const int b0    = bt * HK_BTILE;
    const int myb   = b0 + w * 4;          // this warp's first batch index

    float acc[4][5];
#pragma unroll
    for (int bb = 0; bb < 4; bb++)
#pragma unroll
        for (int k = 0; k < 5; k++) acc[bb][k] = 0.f;

    for (int il = 0; il < HK_ICHUNK; il++) {
        const int i = i0 + il;

        // ---- load W[i] slice for this lane's 5 (j,d) pairs, all 8 e ----
        float wv[5][8];
        const float* Wi = W + (size_t)i * (NC * En * DV);
#pragma unroll
        for (int k = 0; k < 5; k++) {
            const int jd = lane + 32 * k;
            const int j = jd >> 4, d = jd & 15;
            const float* wp = Wi + j * (En * DV) + d;
#pragma unroll
            for (int e = 0; e < En; e++)
                wv[k][e] = __ldg(wp + e * DV);
        }

        // ---- c0[i, j_k] = softmax over j of bias[i,:] ----
        float lg[5];
#pragma unroll
        for (int k = 0; k < 5; k++) {
            const int j = (lane >> 4) + 2 * k;
            lg[k] = __ldg(&bias[i * NC + j]);
        }
        float m = lg[0];
#pragma unroll
        for (int k = 1; k < 5; k++) m = fmaxf(m, lg[k]);
        m = fmaxf(m, __shfl_xor_sync(0xffffffffu, m, 16));
        float se = 0.f;
#pragma unroll
        for (int k = 0; k < 5; k++) { lg[k] = __expf(lg[k] - m); se += lg[k]; }
        se += __shfl_xor_sync(0xffffffffu, se, 16);
        const float inv = __fdividef(1.f, se);
        float c0[5];
#pragma unroll
        for (int k = 0; k < 5; k++) c0[k] = lg[k] * inv;

        // ---- 4 batches reuse the same W registers ----
#pragma unroll
        for (int bb = 0; bb < 4; bb++) {
            const int b = myb + bb;
            const float4* xp =
                reinterpret_cast<const float4*>(x + (size_t)b * (IC * En) + (size_t)i * En);
            const float4 x0 = __ldg(xp);
            const float4 x1 = __ldg(xp + 1);
            float xv[8] = {x0.x, x0.y, x0.z, x0.w, x1.x, x1.y, x1.z, x1.w};

            float* hp = g_hat + ((size_t)b * IC + i) * JD;
#pragma unroll
            for (int k = 0; k < 5; k++) {
                float s = 0.f;
#pragma unroll
                for (int e = 0; e < En; e++) s = fmaf(xv[e], wv[k][e], s);
                hp[lane + 32 * k] = s;
                acc[bb][k] = fmaf(c0[k], s, acc[bb][k]);
            }
        }
    }

    // write pass-0 partial sums (each b owned by exactly one warp)
#pragma unroll
    for (int bb = 0; bb < 4; bb++) {
        const int b = myb + bb;
        float* pp = g_part + ((size_t)b * HK_NCHUNK + chunk) * JD;
#pragma unroll
        for (int k = 0; k < 5; k++) pp[lane + 32 * k] = acc[bb][k];
    }
}

// ---------------------------------------------------------------------------
// Kernel 2: routing pass (reads hat once).
// For each (b,i): a[j] = <hat[b,i,j,:], u[b,j,:]>; logit = bias[i,j] + a[j];
// c = softmax_j(logit); partial s[b,j,d] += c[j]*hat[b,i,j,d].
// Grid: (9 i-chunks, 256 b), 256 threads. Warp w handles i in [chunk*128+w*16, +16).
// ---------------------------------------------------------------------------
__global__ __launch_bounds__(256) void pass_kernel(const float* __restrict__ bias)
{
    const int chunk = blockIdx.x;   // 0..8
    const int b     = blockIdx.y;   // 0..255
    const int tid   = threadIdx.x;
    const int w     = tid >> 5;
    const int lane  = tid & 31;

    __shared__ float us[JD];
    __shared__ float sacc[8 * JD];

    if (tid < JD) us[tid] = g_u[(size_t)b * JD + tid];
    __syncthreads();

    float u[5];
#pragma unroll
    for (int k = 0; k < 5; k++) u[k] = us[lane + 32 * k];

    float acc[5] = {0.f, 0.f, 0.f, 0.f, 0.f};
    const int i0 = chunk * PK_ICHUNK + w * 16;
    const float* hp0 = g_hat + ((size_t)b * IC + i0) * JD;

    for (int t = 0; t < 16; t++) {
        const float* hp = hp0 + (size_t)t * JD;
        float h[5], p[5];
#pragma unroll
        for (int k = 0; k < 5; k++) h[k] = __ldg(hp + lane + 32 * k);
#pragma unroll
        for (int k = 0; k < 5; k++) p[k] = h[k] * u[k];

        // reduce over d (16 lanes per j): butterflies within half-warp groups
#pragma unroll
        for (int off = 1; off < 16; off <<= 1) {
#pragma unroll
            for (int k = 0; k < 5; k++)
                p[k] += __shfl_xor_sync(0xffffffffu, p[k], off);
        }

        const int i = i0 + t;
#pragma unroll
        for (int k = 0; k < 5; k++) {
            const int j = (lane >> 4) + 2 * k;
            p[k] += __ldg(&bias[i * NC + j]);
        }

        // softmax over 10 j's (5 here + 5 in partner half-warp)
        float m = p[0];
#pragma unroll
        for (int k = 1; k < 5; k++) m = fmaxf(m, p[k]);
        m = fmaxf(m, __shfl_xor_sync(0xffffffffu, m, 16));
        float se = 0.f;
#pragma unroll
        for (int k = 0; k < 5; k++) { p[k] = __expf(p[k] - m); se += p[k]; }
        se += __shfl_xor_sync(0xffffffffu, se, 16);
        const float inv = __fdividef(1.f, se);

#pragma unroll
        for (int k = 0; k < 5; k++) acc[k] = fmaf(p[k] * inv, h[k], acc[k]);
    }

#pragma unroll
    for (int k = 0; k < 5; k++) sacc[w * JD + lane + 32 * k] = acc[k];
    __syncthreads();

    if (tid < JD) {
        float s = 0.f;
#pragma unroll
        for (int w2 = 0; w2 < 8; w2++) s += sacc[w2 * JD + tid];
        g_part[((size_t)b * HK_NCHUNK + chunk) * JD + tid] = s;
    }
}

// ---------------------------------------------------------------------------
// Kernel 3: reduce partials -> s, squash -> v, update g_u / write output.
// mode 0: g_u = v (after pass 0);  mode 1: g_u += v;  mode 2: out = v (final).
// Grid: 256 blocks (one per b), 160 threads (one per jd).
// ---------------------------------------------------------------------------
__global__ __launch_bounds__(JD) void squash_kernel(int nch, int mode, float* __restrict__ out)
{
    const int b = blockIdx.x;
    const int tid = threadIdx.x;          // jd
    __shared__ float s[JD];
    __shared__ float scale[NC];

    float a = 0.f;
    for (int c = 0; c < nch; c++)
        a += g_part[((size_t)b * HK_NCHUNK + c) * JD + tid];
    s[tid] = a;
    __syncthreads();

    if (tid < NC) {
        float s2 = 0.f;
#pragma unroll
        for (int d = 0; d < DV; d++) { float v = s[tid * DV + d]; s2 = fmaf(v, v, s2); }
        scale[tid] = s2 / (1.0f + s2) * rsqrtf(s2);
    }
    __syncthreads();

    const float v = scale[tid >> 4] * s[tid];
    if (mode == 0)      g_u[(size_t)b * JD + tid] = v;
    else if (mode == 1) g_u[(size_t)b * JD + tid] += v;
    else                out[(size_t)b * JD + tid] = v;
}

// ---------------------------------------------------------------------------
extern "C" void kernel_launch(void* const* d_in, const int* in_sizes, int n_in,
                              void* d_out, int out_size)
{
    const float* x    = (const float*)d_in[0];   // [256,1152,8]
    const float* W    = (const float*)d_in[1];   // [1152,10,8,16]
    const float* bias = (const float*)d_in[2];   // [1,1152,10]
    float* out        = (float*)d_out;           // [256,10,16]

    // Pass 0 folded into hat production (c0 = softmax(bias), batch-independent)
    hat_s0_kernel<<<dim3(HK_NCHUNK, HK_NBT), 256>>>(x, W, bias);
    squash_kernel<<<Bn, JD>>>(HK_NCHUNK, 0, out);   // v0 -> g_u

    // Pass 1: logits = bias + <hat, v0>
    pass_kernel<<<dim3(PK_NCHUNK, Bn), 256>>>(bias);
    squash_kernel<<<Bn, JD>>>(PK_NCHUNK, 1, out);   // g_u = v0 + v1

    // Pass 2: logits = bias + <hat, v0+v1>  (telescoped b_logits)
    pass_kernel<<<dim3(PK_NCHUNK, Bn), 256>>>(bias);
    squash_kernel<<<Bn, JD>>>(PK_NCHUNK, 2, out);   // output = v2
}